// round 2
// baseline (speedup 1.0000x reference)
#include <cuda_runtime.h>
#include <cstdint>
#include <cstddef>

#define NNODE 1500
#define T_IN  168
#define TLEN  162
#define BATCH 8
#define CH    16
#define EMBD  16
#define KTOP  12
#define NBRS  13                 // KTOP + self
#define FDIM  (BATCH*CH*TLEN)    // 20736
#define ALPHA 1.5f
#define BETA  0.2f

#define PCH   16                 // f-chunk per prop block
#define PPAD  17                 // padded row stride in prop smem

// ---------------- device scratch (no allocations allowed) ----------------
__device__ float g_H0[(size_t)NNODE * FDIM];
__device__ float g_P1[(size_t)NNODE * FDIM];
__device__ float g_P2[(size_t)NNODE * FDIM];
__device__ float g_m1[NNODE * EMBD];
__device__ float g_m2[NNODE * EMBD];
__device__ float g_weff[CH * 8];
__device__ float g_beff[CH];
__device__ int   g_nbr[NNODE * NBRS];
__device__ float g_nw [NNODE * NBRS];
__device__ float2 g_gpack[16 * 48];    // folded G0|G1|G2, duplicated pairs
__device__ float2 g_r1pack[16 * 16];   // rw1, duplicated pairs

// ---------------- constant weights ----------------
__constant__ float c_mb [16];
__constant__ float c_rb1[16];
__constant__ float c_rw2[24 * 16];
__constant__ float c_rb2[24];

// ---------------- packed fp32x2 FMA (sm_103a FFMA2) ----------------
__device__ __forceinline__ float2 ffma2(float2 a, float2 b, float2 c) {
    unsigned long long au = *reinterpret_cast<unsigned long long*>(&a);
    unsigned long long bu = *reinterpret_cast<unsigned long long*>(&b);
    unsigned long long cu = *reinterpret_cast<unsigned long long*>(&c);
    unsigned long long du;
    asm("fma.rn.f32x2 %0, %1, %2, %3;" : "=l"(du) : "l"(au), "l"(bu), "l"(cu));
    return *reinterpret_cast<float2*>(&du);
}

// ============ K0a: fold pw/pb into the inception conv weights ============
__global__ void k_prep_weff(const float* pw, const float* pb,
                            const float* tw2, const float* tb2,
                            const float* tw3, const float* tb3,
                            const float* tw6, const float* tb6,
                            const float* tw7, const float* tb7) {
    int c = threadIdx.x;
    if (c >= CH) return;
    int br = c >> 2, o = c & 3;
    const float* tw; const float* tb; int k;
    if      (br == 0) { tw = tw2; tb = tb2; k = 2; }
    else if (br == 1) { tw = tw3; tb = tb3; k = 3; }
    else if (br == 2) { tw = tw6; tb = tb6; k = 6; }
    else              { tw = tw7; tb = tb7; k = 7; }
    float bacc = tb[o];
    for (int j = 0; j < k; j++) {
        float wacc = 0.f;
        for (int ci = 0; ci < CH; ci++) {
            float w = tw[(o * CH + ci) * k + j];
            wacc += w * pw[ci];
            bacc += w * pb[ci];
        }
        g_weff[c * 8 + j] = wacc;
    }
    g_beff[c] = bacc;
}

// ============ K0b: node embeddings -> m1, m2 ============
__global__ void k_prep_m(const float* e1, const float* gw1, const float* gb1,
                         const float* e2, const float* gw2, const float* gb2) {
    int n = blockIdx.x * blockDim.x + threadIdx.x;
    if (n >= NNODE) return;
    float ev1[EMBD], ev2[EMBD];
#pragma unroll
    for (int i = 0; i < EMBD; i++) { ev1[i] = e1[n * EMBD + i]; ev2[i] = e2[n * EMBD + i]; }
#pragma unroll
    for (int e = 0; e < EMBD; e++) {
        float a1 = gb1[e], a2 = gb2[e];
#pragma unroll
        for (int k = 0; k < EMBD; k++) {
            a1 += ev1[k] * gw1[k * EMBD + e];
            a2 += ev2[k] * gw2[k * EMBD + e];
        }
        g_m1[n * EMBD + e] = tanhf(ALPHA * a1);
        g_m2[n * EMBD + e] = tanhf(ALPHA * a2);
    }
}

// ============ K0c: fold hop blend into the first MLP layer; pack pairs ============
__global__ void k_prep_g(const float* mw, const float* rw1) {
    int tid = threadIdx.x + blockIdx.x * blockDim.x;   // 1024 threads, 1 block
    if (tid < 768) {
        int j = tid / 48, c = tid % 48;
        int hop = c >> 4, ci = c & 15;
        const float* row = mw + j * 48;
        float m1v = row[16 + ci], m2v = row[32 + ci];
        float g;
        if      (hop == 0) g = row[ci] + BETA * m1v + BETA * m2v;
        else if (hop == 1) g = (1.f - BETA) * m1v + BETA * (1.f - BETA) * m2v;
        else               g = (1.f - BETA) * (1.f - BETA) * m2v;
        g_gpack[tid] = make_float2(g, g);
    }
    if (tid < 256) {
        float w = rw1[tid];
        g_r1pack[tid] = make_float2(w, w);
    }
}

// ============ K1: per-row scores + iterative top-12 + row-normalize ============
__global__ void k_topk() {
    int v = blockIdx.x;
    int tid = threadIdx.x;
    __shared__ float s[NNODE];
    __shared__ float rv[256];
    __shared__ int   ri[256];
    __shared__ float selv[KTOP];

    float m1v[EMBD], m2v[EMBD];
#pragma unroll
    for (int e = 0; e < EMBD; e++) { m1v[e] = g_m1[v * EMBD + e]; m2v[e] = g_m2[v * EMBD + e]; }

    for (int w = tid; w < NNODE; w += 256) {
        float d = 0.f;
#pragma unroll
        for (int e = 0; e < EMBD; e++)
            d += m1v[e] * g_m2[w * EMBD + e] - m2v[e] * g_m1[w * EMBD + e];
        float a = tanhf(ALPHA * d);
        s[w] = a > 0.f ? a : 0.f;
    }
    __syncthreads();

    for (int it = 0; it < KTOP; it++) {
        float best = -1.f; int bi = NNODE;
        for (int w = tid; w < NNODE; w += 256) {
            float val = s[w];
            if (val > best || (val == best && w < bi)) { best = val; bi = w; }
        }
        rv[tid] = best; ri[tid] = bi;
        __syncthreads();
        for (int off = 128; off; off >>= 1) {
            if (tid < off) {
                if (rv[tid + off] > rv[tid] ||
                    (rv[tid + off] == rv[tid] && ri[tid + off] < ri[tid])) {
                    rv[tid] = rv[tid + off]; ri[tid] = ri[tid + off];
                }
            }
            __syncthreads();
        }
        if (tid == 0) {
            int bw = ri[0];
            selv[it] = rv[0];
            g_nbr[v * NBRS + it] = bw;
            s[bw] = -2.f;
        }
        __syncthreads();
    }
    if (tid == 0) {
        float rs = 1.f;                       // + identity
        for (int i = 0; i < KTOP; i++) rs += selv[i];
        float inv = 1.f / rs;
        for (int i = 0; i < KTOP; i++) g_nw[v * NBRS + i] = selv[i] * inv;
        g_nbr[v * NBRS + KTOP] = v;
        g_nw [v * NBRS + KTOP] = inv;         // self (identity) weight
    }
}

// ============ K2: folded inception temporal conv -> H0[N][b][c][t] ============
__device__ __forceinline__ constexpr int KC(int c) {
    return c < 4 ? 2 : (c < 8 ? 3 : (c < 12 ? 6 : 7));
}

__global__ void k_tconv(const float* __restrict__ x) {
    int n = blockIdx.x;
    int tid = threadIdx.x;                    // 192 threads
    __shared__ float xs[BATCH][T_IN];
    __shared__ float swv[128];
    __shared__ float sbv[16];
    for (int i = tid; i < BATCH * T_IN; i += 192) {
        int b = i / T_IN, t = i - b * T_IN;
        xs[b][t] = x[(size_t)(b * T_IN + t) * NNODE + n];
    }
    if (tid < 128) swv[tid] = g_weff[tid];
    if (tid < 16)  sbv[tid] = g_beff[tid];
    __syncthreads();
    if (tid >= TLEN) return;

    // hoist weights into registers (uniform across warp)
    float wr[16][8];
#pragma unroll
    for (int c = 0; c < 16; c++) {
        const int k = KC(c);
#pragma unroll
        for (int j = 0; j < 8; j++)
            if (j < k) wr[c][j] = swv[c * 8 + j];
    }
    float bb[16];
#pragma unroll
    for (int c = 0; c < 16; c++) bb[c] = sbv[c];

    float* outp = g_H0 + (size_t)n * FDIM + tid;
#pragma unroll
    for (int b = 0; b < BATCH; b++) {
#pragma unroll
        for (int c = 0; c < 16; c++) {
            const int k = KC(c);
            float acc = bb[c];
#pragma unroll
            for (int j = 0; j < k; j++)
                acc = fmaf(wr[c][j], xs[b][tid + 7 - k + j], acc);
            outp[(size_t)(b * 16 + c) * TLEN] = fmaxf(acc, 0.f);
        }
    }
}

// ============ K3/K4: pure propagation P = Â · src, smem-resident f-chunk ============
__global__ void k_prop(const float* __restrict__ src, float* __restrict__ dst) {
    extern __shared__ float S[];              // [NNODE][PPAD]
    int base = blockIdx.x * PCH;
    int tid = threadIdx.x;                    // 1024 threads

    for (int idx = tid; idx < NNODE * PCH; idx += 1024) {
        int nn = idx >> 4, i = idx & 15;
        S[nn * PPAD + i] = src[(size_t)nn * FDIM + base + i];
    }
    __syncthreads();

    int lane = tid & 31, w = tid >> 5;
    int half = lane >> 4, i = lane & 15;
    for (int v = w * 2 + half; v < NNODE; v += 64) {
        const int*   nbp = g_nbr + v * NBRS;
        const float* nwp = g_nw  + v * NBRS;
        float acc = 0.f;
#pragma unroll
        for (int j = 0; j < NBRS; j++)
            acc += nwp[j] * S[nbp[j] * PPAD + i];
        dst[(size_t)v * FDIM + base + i] = acc;
    }
}

// ============ K5: fused MLP head with f32x2, time-mean, 16->24 ============
__global__ void k_final(float* __restrict__ out) {
    int v = blockIdx.x;
    int b = blockIdx.y;
    int tid = threadIdx.x;                    // 96 threads, 81 active pairs
    __shared__ float2 sg[768];
    __shared__ float2 sr1[256];
    __shared__ float part[3][16];
    __shared__ float rm[16];

    for (int i = tid; i < 768; i += 96) sg[i]  = g_gpack[i];
    for (int i = tid; i < 256; i += 96) sr1[i] = g_r1pack[i];
    __syncthreads();

    bool act = tid < 81;
    int t0 = act ? 2 * tid : 0;
    size_t off = (size_t)v * FDIM + (size_t)b * (CH * TLEN) + t0;

    float2 z[16];
#pragma unroll
    for (int j = 0; j < 16; j++) { float m = c_mb[j]; z[j] = make_float2(m, m); }

#pragma unroll
    for (int s = 0; s < 3; s++) {
        const float* bp = (s == 0 ? g_H0 : (s == 1 ? g_P1 : g_P2)) + off;
        float2 h[16];
#pragma unroll
        for (int c = 0; c < 16; c++)
            h[c] = *reinterpret_cast<const float2*>(bp + (size_t)c * TLEN);
#pragma unroll
        for (int j = 0; j < 16; j++) {
#pragma unroll
            for (int c = 0; c < 16; c++)
                z[j] = ffma2(sg[j * 48 + s * 16 + c], h[c], z[j]);
        }
    }

    // relu on both halves, repack
    float2 zr[16];
#pragma unroll
    for (int j = 0; j < 16; j++)
        zr[j] = make_float2(fmaxf(z[j].x, 0.f), fmaxf(z[j].y, 0.f));

    float rsum[16];
#pragma unroll
    for (int i = 0; i < 16; i++) {
        float rb = c_rb1[i];
        float2 acc = make_float2(rb, rb);
#pragma unroll
        for (int j = 0; j < 16; j++)
            acc = ffma2(sr1[i * 16 + j], zr[j], acc);
        float sres = fmaxf(acc.x, 0.f) + fmaxf(acc.y, 0.f);
        rsum[i] = act ? sres : 0.f;
    }

    // block reduce over t (3 warps)
    int lane = tid & 31, w = tid >> 5;
#pragma unroll
    for (int i = 0; i < 16; i++) {
        float sres = rsum[i];
#pragma unroll
        for (int o = 16; o; o >>= 1) sres += __shfl_xor_sync(0xffffffffu, sres, o);
        if (lane == 0) part[w][i] = sres;
    }
    __syncthreads();
    if (tid < 16)
        rm[tid] = (part[0][tid] + part[1][tid] + part[2][tid]) * (1.f / (float)TLEN);
    __syncthreads();
    if (tid < 24) {
        float a = c_rb2[tid];
#pragma unroll
        for (int c = 0; c < 16; c++) a += c_rw2[tid * 16 + c] * rm[c];
        out[((size_t)b * 24 + tid) * NNODE + v] = a;
    }
}

// ======================= launcher =======================
extern "C" void kernel_launch(void* const* d_in, const int* in_sizes, int n_in,
                              void* d_out, int out_size) {
    const float* x   = (const float*)d_in[0];
    const float* pw  = (const float*)d_in[1];
    const float* pb  = (const float*)d_in[2];
    const float* tw2 = (const float*)d_in[3];
    const float* tb2 = (const float*)d_in[4];
    const float* tw3 = (const float*)d_in[5];
    const float* tb3 = (const float*)d_in[6];
    const float* tw6 = (const float*)d_in[7];
    const float* tb6 = (const float*)d_in[8];
    const float* tw7 = (const float*)d_in[9];
    const float* tb7 = (const float*)d_in[10];
    const float* e1  = (const float*)d_in[11];
    const float* e2  = (const float*)d_in[12];
    const float* gw1 = (const float*)d_in[13];
    const float* gb1 = (const float*)d_in[14];
    const float* gw2 = (const float*)d_in[15];
    const float* gb2 = (const float*)d_in[16];
    const float* mw  = (const float*)d_in[17];
    const float* rw1 = (const float*)d_in[19];

    static bool attr_set = false;
    if (!attr_set) {
        cudaFuncSetAttribute(k_prop, cudaFuncAttributeMaxDynamicSharedMemorySize,
                             NNODE * PPAD * (int)sizeof(float));
        attr_set = true;
    }

    cudaMemcpyToSymbolAsync(c_mb,  d_in[18], 16 * sizeof(float),      0, cudaMemcpyDeviceToDevice, 0);
    cudaMemcpyToSymbolAsync(c_rb1, d_in[20], 16 * sizeof(float),      0, cudaMemcpyDeviceToDevice, 0);
    cudaMemcpyToSymbolAsync(c_rw2, d_in[21], 24 * 16 * sizeof(float), 0, cudaMemcpyDeviceToDevice, 0);
    cudaMemcpyToSymbolAsync(c_rb2, d_in[22], 24 * sizeof(float),      0, cudaMemcpyDeviceToDevice, 0);

    k_prep_weff<<<1, 32>>>(pw, pb, tw2, tb2, tw3, tb3, tw6, tb6, tw7, tb7);
    k_prep_m<<<(NNODE + 127) / 128, 128>>>(e1, gw1, gb1, e2, gw2, gb2);
    k_prep_g<<<1, 1024>>>(mw, rw1);
    k_topk<<<NNODE, 256>>>();
    k_tconv<<<NNODE, 192>>>(x);

    float* H0 = nullptr; float* P1 = nullptr; float* P2 = nullptr;
    cudaGetSymbolAddress((void**)&H0, g_H0);
    cudaGetSymbolAddress((void**)&P1, g_P1);
    cudaGetSymbolAddress((void**)&P2, g_P2);

    int smem = NNODE * PPAD * (int)sizeof(float);
    k_prop<<<FDIM / PCH, 1024, smem>>>(H0, P1);
    k_prop<<<FDIM / PCH, 1024, smem>>>(P1, P2);

    dim3 gf(NNODE, BATCH);
    k_final<<<gf, 96>>>((float*)d_out);
}

// round 4
// speedup vs baseline: 1.0020x; 1.0020x over previous
#include <cuda_runtime.h>
#include <cstdint>
#include <cstddef>
#include <climits>

#define NNODE 1500
#define T_IN  168
#define TLEN  162
#define BATCH 8
#define CH    16
#define EMBD  16
#define KTOP  12
#define NBRS  13            // KTOP + self
#define FDIM  (BATCH*CH*TLEN)   // 20736
#define ALPHA 1.5f
#define BETA  0.2f

// ---------------- device scratch (no allocations allowed) ----------------
__device__ float g_H0[(size_t)NNODE * FDIM];
__device__ float g_H1[(size_t)NNODE * FDIM];
__device__ float g_H2[(size_t)NNODE * FDIM];
__device__ float g_m1[NNODE * EMBD];
__device__ float g_m2[NNODE * EMBD];
__device__ float g_weff[CH * 8];
__device__ float g_beff[CH];
__device__ int   g_nbr[NNODE * NBRS];
__device__ float g_nw [NNODE * NBRS];

// ---------------- constant weights for the MLP head ----------------
__constant__ float c_mw [16 * 48];
__constant__ float c_mb [16];
__constant__ float c_rw1[16 * 16];
__constant__ float c_rb1[16];
__constant__ float c_rw2[24 * 16];
__constant__ float c_rb2[24];

// ============ K0a: fold pw/pb into the inception conv weights ============
__global__ void k_prep_weff(const float* pw, const float* pb,
                            const float* tw2, const float* tb2,
                            const float* tw3, const float* tb3,
                            const float* tw6, const float* tb6,
                            const float* tw7, const float* tb7) {
    int c = threadIdx.x;
    if (c >= CH) return;
    int br = c >> 2, o = c & 3;
    const float* tw; const float* tb; int k;
    if      (br == 0) { tw = tw2; tb = tb2; k = 2; }
    else if (br == 1) { tw = tw3; tb = tb3; k = 3; }
    else if (br == 2) { tw = tw6; tb = tb6; k = 6; }
    else              { tw = tw7; tb = tb7; k = 7; }
    float bacc = tb[o];
    for (int j = 0; j < k; j++) {
        float wacc = 0.f;
        for (int ci = 0; ci < CH; ci++) {
            float w = tw[(o * CH + ci) * k + j];
            wacc += w * pw[ci];
            bacc += w * pb[ci];
        }
        g_weff[c * 8 + j] = wacc;
    }
    g_beff[c] = bacc;
}

// ============ K0b: node embeddings -> m1, m2 ============
__global__ void k_prep_m(const float* e1, const float* gw1, const float* gb1,
                         const float* e2, const float* gw2, const float* gb2) {
    int n = blockIdx.x * blockDim.x + threadIdx.x;
    if (n >= NNODE) return;
    float ev1[EMBD], ev2[EMBD];
#pragma unroll
    for (int i = 0; i < EMBD; i++) { ev1[i] = e1[n * EMBD + i]; ev2[i] = e2[n * EMBD + i]; }
#pragma unroll
    for (int e = 0; e < EMBD; e++) {
        float a1 = gb1[e], a2 = gb2[e];
#pragma unroll
        for (int k = 0; k < EMBD; k++) {
            a1 += ev1[k] * gw1[k * EMBD + e];
            a2 += ev2[k] * gw2[k * EMBD + e];
        }
        g_m1[n * EMBD + e] = tanhf(ALPHA * a1);
        g_m2[n * EMBD + e] = tanhf(ALPHA * a2);
    }
}

// ============ K1: warp-level tournament top-12 (no barriers in hot loop) ============
#define SEG 188                       // ceil(1500 / 8)
#define SLOTS 6                       // ceil(SEG / 32)

__global__ void k_topk() {
    int v = blockIdx.x;
    int tid = threadIdx.x;            // 256 threads, 8 warps
    int w = tid >> 5, lane = tid & 31;

    // row-v embeddings (broadcast, L1-resident)
    float m1v[EMBD], m2v[EMBD];
#pragma unroll
    for (int e = 0; e < EMBD; e++) { m1v[e] = g_m1[v * EMBD + e]; m2v[e] = g_m2[v * EMBD + e]; }

    // each warp computes scores for its segment directly into registers
    int base = w * SEG;
    int segEnd = min(base + SEG, NNODE);
    float vals[SLOTS];
    int   idxs[SLOTS];
#pragma unroll
    for (int k = 0; k < SLOTS; k++) {
        int idx = base + k * 32 + lane;
        if (idx < segEnd) {
            const float4* p2 = (const float4*)(g_m2 + idx * EMBD);
            const float4* p1 = (const float4*)(g_m1 + idx * EMBD);
            float d = 0.f;
#pragma unroll
            for (int q = 0; q < 4; q++) {
                float4 a2 = p2[q], a1 = p1[q];
                d += m1v[4*q+0]*a2.x - m2v[4*q+0]*a1.x;
                d += m1v[4*q+1]*a2.y - m2v[4*q+1]*a1.y;
                d += m1v[4*q+2]*a2.z - m2v[4*q+2]*a1.z;
                d += m1v[4*q+3]*a2.w - m2v[4*q+3]*a1.w;
            }
            float a = tanhf(ALPHA * d);
            vals[k] = a > 0.f ? a : 0.f;
            idxs[k] = idx;
        } else {
            vals[k] = -1.f;
            idxs[k] = INT_MAX;
        }
    }

    __shared__ float swv[8][KTOP];
    __shared__ int   swi[8][KTOP];

    // warp-local top-12 via shfl-butterfly argmax
#pragma unroll
    for (int it = 0; it < KTOP; it++) {
        float bv = -1.f; int bi = INT_MAX;
#pragma unroll
        for (int k = 0; k < SLOTS; k++)
            if (vals[k] > bv || (vals[k] == bv && idxs[k] < bi)) { bv = vals[k]; bi = idxs[k]; }
#pragma unroll
        for (int off = 16; off; off >>= 1) {
            float ov = __shfl_xor_sync(0xffffffffu, bv, off);
            int   oi = __shfl_xor_sync(0xffffffffu, bi, off);
            if (ov > bv || (ov == bv && oi < bi)) { bv = ov; bi = oi; }
        }
        // remove winner from owner lane
#pragma unroll
        for (int k = 0; k < SLOTS; k++)
            if (idxs[k] == bi) vals[k] = -1.f;
        if (lane == 0) { swv[w][it] = bv; swi[w][it] = bi; }
    }
    __syncthreads();

    // warp 0 merges 96 candidates (3 per lane)
    if (w == 0) {
        float mv[3]; int mi[3];
#pragma unroll
        for (int k = 0; k < 3; k++) {
            int j = lane + 32 * k;
            if (j < 96) { mv[k] = swv[j / KTOP][j % KTOP]; mi[k] = swi[j / KTOP][j % KTOP]; }
            else        { mv[k] = -1.f; mi[k] = INT_MAX; }
        }
        float myv = -1.f; int myi = 0;     // lane 'it' keeps winner 'it'
        float sum = 0.f;
#pragma unroll
        for (int it = 0; it < KTOP; it++) {
            float bv = -1.f; int bi = INT_MAX;
#pragma unroll
            for (int k = 0; k < 3; k++)
                if (mv[k] > bv || (mv[k] == bv && mi[k] < bi)) { bv = mv[k]; bi = mi[k]; }
#pragma unroll
            for (int off = 16; off; off >>= 1) {
                float ov = __shfl_xor_sync(0xffffffffu, bv, off);
                int   oi = __shfl_xor_sync(0xffffffffu, bi, off);
                if (ov > bv || (ov == bv && oi < bi)) { bv = ov; bi = oi; }
            }
#pragma unroll
            for (int k = 0; k < 3; k++)
                if (mi[k] == bi) mv[k] = -1.f;
            if (lane == it) { myv = bv; myi = bi; }
            sum += bv;
        }
        float inv = 1.f / (1.f + sum);
        if (lane < KTOP) {
            g_nbr[v * NBRS + lane] = myi;
            g_nw [v * NBRS + lane] = myv * inv;
        }
        if (lane == 0) {
            g_nbr[v * NBRS + KTOP] = v;
            g_nw [v * NBRS + KTOP] = inv;
        }
    }
}

// ============ K2: folded inception temporal conv -> H0[N][b][c][t] ============
__device__ __forceinline__ constexpr int KC(int c) {
    return c < 4 ? 2 : (c < 8 ? 3 : (c < 12 ? 6 : 7));
}

__global__ void k_tconv(const float* __restrict__ x) {
    int n = blockIdx.x;
    int tid = threadIdx.x;                    // 192 threads
    __shared__ float xs[BATCH][T_IN];
    __shared__ float swv[128];
    __shared__ float sbv[16];
    for (int i = tid; i < BATCH * T_IN; i += 192) {
        int b = i / T_IN, t = i - b * T_IN;
        xs[b][t] = x[(size_t)(b * T_IN + t) * NNODE + n];
    }
    if (tid < 128) swv[tid] = g_weff[tid];
    if (tid < 16)  sbv[tid] = g_beff[tid];
    __syncthreads();
    if (tid >= TLEN) return;

    float wr[16][8];
#pragma unroll
    for (int c = 0; c < 16; c++) {
        const int k = KC(c);
#pragma unroll
        for (int j = 0; j < 8; j++)
            if (j < k) wr[c][j] = swv[c * 8 + j];
    }
    float bb[16];
#pragma unroll
    for (int c = 0; c < 16; c++) bb[c] = sbv[c];

    float* outp = g_H0 + (size_t)n * FDIM + tid;
#pragma unroll
    for (int b = 0; b < BATCH; b++) {
#pragma unroll
        for (int c = 0; c < 16; c++) {
            const int k = KC(c);
            float acc = bb[c];
#pragma unroll
            for (int j = 0; j < k; j++)
                acc = fmaf(wr[c][j], xs[b][tid + 7 - k + j], acc);
            outp[(size_t)(b * 16 + c) * TLEN] = fmaxf(acc, 0.f);
        }
    }
}

// ============ K3/K4: sparse mixprop hop (13 nnz/row SpMM via L2) ============
__global__ void k_spmm(int hop) {
    int v = blockIdx.x;
    int f = blockIdx.y * 256 + threadIdx.x;
    __shared__ int   nb[NBRS];
    __shared__ float nw[NBRS];
    if (threadIdx.x < NBRS) {
        nb[threadIdx.x] = g_nbr[v * NBRS + threadIdx.x];
        nw[threadIdx.x] = g_nw [v * NBRS + threadIdx.x];
    }
    __syncthreads();
    const float* src = hop ? g_H1 : g_H0;
    float acc = 0.f;
#pragma unroll
    for (int i = 0; i < NBRS; i++)
        acc += nw[i] * src[(size_t)nb[i] * FDIM + f];
    float h0v = g_H0[(size_t)v * FDIM + f];
    float* dst = hop ? g_H2 : g_H1;
    dst[(size_t)v * FDIM + f] = BETA * h0v + (1.f - BETA) * acc;
}

// ============ K5: MLP head (48->16 relu ->16 relu), time-mean, 16->24 ============
__global__ void k_final(float* __restrict__ out) {
    int v = blockIdx.x;
    int b = blockIdx.y;
    int tid = threadIdx.x;
    bool valid = tid < TLEN;
    int t = valid ? tid : 0;

    size_t base = (size_t)v * FDIM + (size_t)(b * CH) * TLEN + t;
    float ho[48];
#pragma unroll
    for (int c = 0; c < CH; c++) {
        ho[c]      = g_H0[base + (size_t)c * TLEN];
        ho[16 + c] = g_H1[base + (size_t)c * TLEN];
        ho[32 + c] = g_H2[base + (size_t)c * TLEN];
    }
    float z[16];
#pragma unroll
    for (int j = 0; j < 16; j++) {
        float a = c_mb[j];
#pragma unroll
        for (int c = 0; c < 48; c++) a += c_mw[j * 48 + c] * ho[c];
        z[j] = fmaxf(a, 0.f);
    }
    float r[16];
#pragma unroll
    for (int i = 0; i < 16; i++) {
        float a = c_rb1[i];
#pragma unroll
        for (int j = 0; j < 16; j++) a += c_rw1[i * 16 + j] * z[j];
        r[i] = valid ? fmaxf(a, 0.f) : 0.f;
    }

    // block-reduce sum over t
    __shared__ float part[6][16];
    __shared__ float rm[16];
    int warp = tid >> 5, lane = tid & 31;
#pragma unroll
    for (int c = 0; c < 16; c++) {
        float s = r[c];
#pragma unroll
        for (int off = 16; off; off >>= 1) s += __shfl_xor_sync(0xffffffffu, s, off);
        if (lane == 0) part[warp][c] = s;
    }
    __syncthreads();
    if (tid < 16) {
        float s = 0.f;
#pragma unroll
        for (int w = 0; w < 6; w++) s += part[w][tid];
        rm[tid] = s * (1.f / (float)TLEN);
    }
    __syncthreads();
    if (tid < 24) {
        float a = c_rb2[tid];
#pragma unroll
        for (int c = 0; c < 16; c++) a += c_rw2[tid * 16 + c] * rm[c];
        out[((size_t)b * 24 + tid) * NNODE + v] = a;
    }
}

// ======================= launcher =======================
extern "C" void kernel_launch(void* const* d_in, const int* in_sizes, int n_in,
                              void* d_out, int out_size) {
    const float* x   = (const float*)d_in[0];
    const float* pw  = (const float*)d_in[1];
    const float* pb  = (const float*)d_in[2];
    const float* tw2 = (const float*)d_in[3];
    const float* tb2 = (const float*)d_in[4];
    const float* tw3 = (const float*)d_in[5];
    const float* tb3 = (const float*)d_in[6];
    const float* tw6 = (const float*)d_in[7];
    const float* tb6 = (const float*)d_in[8];
    const float* tw7 = (const float*)d_in[9];
    const float* tb7 = (const float*)d_in[10];
    const float* e1  = (const float*)d_in[11];
    const float* e2  = (const float*)d_in[12];
    const float* gw1 = (const float*)d_in[13];
    const float* gb1 = (const float*)d_in[14];
    const float* gw2 = (const float*)d_in[15];
    const float* gb2 = (const float*)d_in[16];

    cudaMemcpyToSymbolAsync(c_mw,  d_in[17], 16 * 48 * sizeof(float), 0, cudaMemcpyDeviceToDevice, 0);
    cudaMemcpyToSymbolAsync(c_mb,  d_in[18], 16 * sizeof(float),      0, cudaMemcpyDeviceToDevice, 0);
    cudaMemcpyToSymbolAsync(c_rw1, d_in[19], 16 * 16 * sizeof(float), 0, cudaMemcpyDeviceToDevice, 0);
    cudaMemcpyToSymbolAsync(c_rb1, d_in[20], 16 * sizeof(float),      0, cudaMemcpyDeviceToDevice, 0);
    cudaMemcpyToSymbolAsync(c_rw2, d_in[21], 24 * 16 * sizeof(float), 0, cudaMemcpyDeviceToDevice, 0);
    cudaMemcpyToSymbolAsync(c_rb2, d_in[22], 24 * sizeof(float),      0, cudaMemcpyDeviceToDevice, 0);

    k_prep_weff<<<1, 32>>>(pw, pb, tw2, tb2, tw3, tb3, tw6, tb6, tw7, tb7);
    k_prep_m<<<(NNODE + 127) / 128, 128>>>(e1, gw1, gb1, e2, gw2, gb2);
    k_topk<<<NNODE, 256>>>();
    k_tconv<<<NNODE, 192>>>(x);

    dim3 gs(NNODE, FDIM / 256);   // 1500 x 81
    k_spmm<<<gs, 256>>>(0);
    k_spmm<<<gs, 256>>>(1);

    dim3 gf(NNODE, BATCH);        // 1500 x 8
    k_final<<<gf, 192>>>((float*)d_out);
}

// round 5
// speedup vs baseline: 1.2889x; 1.2864x over previous
#include <cuda_runtime.h>
#include <cstdint>
#include <cstddef>
#include <climits>

#define NNODE 1500
#define T_IN  168
#define TLEN  162
#define BATCH 8
#define CH    16
#define EMBD  16
#define KTOP  12
#define NBRS  13            // KTOP + self
#define FDIM  (BATCH*CH*TLEN)   // 20736
#define ALPHA 1.5f
#define BETA  0.2f

// ---------------- device scratch (no allocations allowed) ----------------
__device__ float g_H0[(size_t)NNODE * FDIM];
__device__ float g_H1[(size_t)NNODE * FDIM];
__device__ float g_H2[(size_t)NNODE * FDIM];
__device__ float g_m1[NNODE * EMBD];
__device__ float g_m2[NNODE * EMBD];
__device__ float g_weff[CH * 8];
__device__ float g_beff[CH];
__device__ int   g_nbr[NNODE * NBRS];
__device__ float g_nw [NNODE * NBRS];

// ---------------- packed fp32x2 FMA (sm_103a FFMA2) ----------------
__device__ __forceinline__ float2 ffma2(float2 a, float2 b, float2 c) {
    unsigned long long au = *reinterpret_cast<unsigned long long*>(&a);
    unsigned long long bu = *reinterpret_cast<unsigned long long*>(&b);
    unsigned long long cu = *reinterpret_cast<unsigned long long*>(&c);
    unsigned long long du;
    asm("fma.rn.f32x2 %0, %1, %2, %3;" : "=l"(du) : "l"(au), "l"(bu), "l"(cu));
    return *reinterpret_cast<float2*>(&du);
}

// ============ K0a: fold pw/pb into the inception conv weights ============
__global__ void k_prep_weff(const float* pw, const float* pb,
                            const float* tw2, const float* tb2,
                            const float* tw3, const float* tb3,
                            const float* tw6, const float* tb6,
                            const float* tw7, const float* tb7) {
    int c = threadIdx.x;
    if (c >= CH) return;
    int br = c >> 2, o = c & 3;
    const float* tw; const float* tb; int k;
    if      (br == 0) { tw = tw2; tb = tb2; k = 2; }
    else if (br == 1) { tw = tw3; tb = tb3; k = 3; }
    else if (br == 2) { tw = tw6; tb = tb6; k = 6; }
    else              { tw = tw7; tb = tb7; k = 7; }
    float bacc = tb[o];
    for (int j = 0; j < k; j++) {
        float wacc = 0.f;
        for (int ci = 0; ci < CH; ci++) {
            float w = tw[(o * CH + ci) * k + j];
            wacc += w * pw[ci];
            bacc += w * pb[ci];
        }
        g_weff[c * 8 + j] = wacc;
    }
    g_beff[c] = bacc;
}

// ============ K0b: node embeddings -> m1, m2 ============
__global__ void k_prep_m(const float* e1, const float* gw1, const float* gb1,
                         const float* e2, const float* gw2, const float* gb2) {
    int n = blockIdx.x * blockDim.x + threadIdx.x;
    if (n >= NNODE) return;
    float ev1[EMBD], ev2[EMBD];
#pragma unroll
    for (int i = 0; i < EMBD; i++) { ev1[i] = e1[n * EMBD + i]; ev2[i] = e2[n * EMBD + i]; }
#pragma unroll
    for (int e = 0; e < EMBD; e++) {
        float a1 = gb1[e], a2 = gb2[e];
#pragma unroll
        for (int k = 0; k < EMBD; k++) {
            a1 += ev1[k] * gw1[k * EMBD + e];
            a2 += ev2[k] * gw2[k * EMBD + e];
        }
        g_m1[n * EMBD + e] = tanhf(ALPHA * a1);
        g_m2[n * EMBD + e] = tanhf(ALPHA * a2);
    }
}

// ============ K1: warp-level tournament top-12 (no barriers in hot loop) ============
#define SEG 188                       // ceil(1500 / 8)
#define SLOTS 6                       // ceil(SEG / 32)

__global__ void k_topk() {
    int v = blockIdx.x;
    int tid = threadIdx.x;            // 256 threads, 8 warps
    int w = tid >> 5, lane = tid & 31;

    float m1v[EMBD], m2v[EMBD];
#pragma unroll
    for (int e = 0; e < EMBD; e++) { m1v[e] = g_m1[v * EMBD + e]; m2v[e] = g_m2[v * EMBD + e]; }

    int base = w * SEG;
    int segEnd = min(base + SEG, NNODE);
    float vals[SLOTS];
    int   idxs[SLOTS];
#pragma unroll
    for (int k = 0; k < SLOTS; k++) {
        int idx = base + k * 32 + lane;
        if (idx < segEnd) {
            const float4* p2 = (const float4*)(g_m2 + idx * EMBD);
            const float4* p1 = (const float4*)(g_m1 + idx * EMBD);
            float d = 0.f;
#pragma unroll
            for (int q = 0; q < 4; q++) {
                float4 a2 = p2[q], a1 = p1[q];
                d += m1v[4*q+0]*a2.x - m2v[4*q+0]*a1.x;
                d += m1v[4*q+1]*a2.y - m2v[4*q+1]*a1.y;
                d += m1v[4*q+2]*a2.z - m2v[4*q+2]*a1.z;
                d += m1v[4*q+3]*a2.w - m2v[4*q+3]*a1.w;
            }
            float a = tanhf(ALPHA * d);
            vals[k] = a > 0.f ? a : 0.f;
            idxs[k] = idx;
        } else {
            vals[k] = -1.f;
            idxs[k] = INT_MAX;
        }
    }

    __shared__ float swv[8][KTOP];
    __shared__ int   swi[8][KTOP];

#pragma unroll
    for (int it = 0; it < KTOP; it++) {
        float bv = -1.f; int bi = INT_MAX;
#pragma unroll
        for (int k = 0; k < SLOTS; k++)
            if (vals[k] > bv || (vals[k] == bv && idxs[k] < bi)) { bv = vals[k]; bi = idxs[k]; }
#pragma unroll
        for (int off = 16; off; off >>= 1) {
            float ov = __shfl_xor_sync(0xffffffffu, bv, off);
            int   oi = __shfl_xor_sync(0xffffffffu, bi, off);
            if (ov > bv || (ov == bv && oi < bi)) { bv = ov; bi = oi; }
        }
#pragma unroll
        for (int k = 0; k < SLOTS; k++)
            if (idxs[k] == bi) vals[k] = -1.f;
        if (lane == 0) { swv[w][it] = bv; swi[w][it] = bi; }
    }
    __syncthreads();

    if (w == 0) {
        float mv[3]; int mi[3];
#pragma unroll
        for (int k = 0; k < 3; k++) {
            int j = lane + 32 * k;
            if (j < 96) { mv[k] = swv[j / KTOP][j % KTOP]; mi[k] = swi[j / KTOP][j % KTOP]; }
            else        { mv[k] = -1.f; mi[k] = INT_MAX; }
        }
        float myv = -1.f; int myi = 0;
        float sum = 0.f;
#pragma unroll
        for (int it = 0; it < KTOP; it++) {
            float bv = -1.f; int bi = INT_MAX;
#pragma unroll
            for (int k = 0; k < 3; k++)
                if (mv[k] > bv || (mv[k] == bv && mi[k] < bi)) { bv = mv[k]; bi = mi[k]; }
#pragma unroll
            for (int off = 16; off; off >>= 1) {
                float ov = __shfl_xor_sync(0xffffffffu, bv, off);
                int   oi = __shfl_xor_sync(0xffffffffu, bi, off);
                if (ov > bv || (ov == bv && oi < bi)) { bv = ov; bi = oi; }
            }
#pragma unroll
            for (int k = 0; k < 3; k++)
                if (mi[k] == bi) mv[k] = -1.f;
            if (lane == it) { myv = bv; myi = bi; }
            sum += bv;
        }
        float inv = 1.f / (1.f + sum);
        if (lane < KTOP) {
            g_nbr[v * NBRS + lane] = myi;
            g_nw [v * NBRS + lane] = myv * inv;
        }
        if (lane == 0) {
            g_nbr[v * NBRS + KTOP] = v;
            g_nw [v * NBRS + KTOP] = inv;
        }
    }
}

// ============ K2: folded inception temporal conv -> H0[N][b][c][t] ============
__device__ __forceinline__ constexpr int KC(int c) {
    return c < 4 ? 2 : (c < 8 ? 3 : (c < 12 ? 6 : 7));
}

__global__ void k_tconv(const float* __restrict__ x) {
    int n = blockIdx.x;
    int tid = threadIdx.x;                    // 192 threads
    __shared__ float xs[BATCH][T_IN];
    __shared__ float swv[128];
    __shared__ float sbv[16];
    for (int i = tid; i < BATCH * T_IN; i += 192) {
        int b = i / T_IN, t = i - b * T_IN;
        xs[b][t] = x[(size_t)(b * T_IN + t) * NNODE + n];
    }
    if (tid < 128) swv[tid] = g_weff[tid];
    if (tid < 16)  sbv[tid] = g_beff[tid];
    __syncthreads();
    if (tid >= TLEN) return;

    float wr[16][8];
#pragma unroll
    for (int c = 0; c < 16; c++) {
        const int k = KC(c);
#pragma unroll
        for (int j = 0; j < 8; j++)
            if (j < k) wr[c][j] = swv[c * 8 + j];
    }
    float bb[16];
#pragma unroll
    for (int c = 0; c < 16; c++) bb[c] = sbv[c];

    float* outp = g_H0 + (size_t)n * FDIM + tid;
#pragma unroll
    for (int b = 0; b < BATCH; b++) {
#pragma unroll
        for (int c = 0; c < 16; c++) {
            const int k = KC(c);
            float acc = bb[c];
#pragma unroll
            for (int j = 0; j < k; j++)
                acc = fmaf(wr[c][j], xs[b][tid + 7 - k + j], acc);
            outp[(size_t)(b * 16 + c) * TLEN] = fmaxf(acc, 0.f);
        }
    }
}

// ============ K3/K4: sparse mixprop hop (13 nnz/row SpMM via L2) ============
__global__ void k_spmm(int hop) {
    int v = blockIdx.x;
    int f = blockIdx.y * 256 + threadIdx.x;
    __shared__ int   nb[NBRS];
    __shared__ float nw[NBRS];
    if (threadIdx.x < NBRS) {
        nb[threadIdx.x] = g_nbr[v * NBRS + threadIdx.x];
        nw[threadIdx.x] = g_nw [v * NBRS + threadIdx.x];
    }
    __syncthreads();
    const float* src = hop ? g_H1 : g_H0;
    float acc = 0.f;
#pragma unroll
    for (int i = 0; i < NBRS; i++)
        acc += nw[i] * src[(size_t)nb[i] * FDIM + f];
    float h0v = g_H0[(size_t)v * FDIM + f];
    float* dst = hop ? g_H2 : g_H1;
    dst[(size_t)v * FDIM + f] = BETA * h0v + (1.f - BETA) * acc;
}

// ============ K5: MLP head, weights in SMEM, f32x2, 6 t's per thread ============
__global__ __launch_bounds__(224, 2) void k_final(
    const float* __restrict__ mw,  const float* __restrict__ mb,
    const float* __restrict__ rw1, const float* __restrict__ rb1,
    const float* __restrict__ rw2, const float* __restrict__ rb2,
    float* __restrict__ out) {
    int v = blockIdx.x;
    int tid = threadIdx.x;                 // 224 threads; 216 active in main phase
    __shared__ float2 sg[768];             // mw dup pairs: [j][hop*16+c]
    __shared__ float2 sr1[256];            // rw1 dup pairs
    __shared__ float  s_mb[16], s_rb1[16], s_rw2[384], s_rb2[24];
    __shared__ float  part[216][16];
    __shared__ float  rm[8][16];

    for (int idx = tid; idx < 768; idx += 224) { float w = mw[idx];  sg[idx]  = make_float2(w, w); }
    for (int idx = tid; idx < 256; idx += 224) { float w = rw1[idx]; sr1[idx] = make_float2(w, w); }
    for (int idx = tid; idx < 384; idx += 224) s_rw2[idx] = rw2[idx];
    if (tid < 16) { s_mb[tid] = mb[tid]; s_rb1[tid] = rb1[tid]; }
    if (tid < 24) s_rb2[tid] = rb2[tid];
    __syncthreads();

    if (tid < 216) {
        int b = tid / 27;
        int i = tid - b * 27;
        int t0 = i * 6;                    // 27*6 = 162 exactly
        size_t off = (size_t)v * FDIM + (size_t)b * (CH * TLEN) + t0;

        float2 z0[16], z1[16], z2[16];
#pragma unroll
        for (int j = 0; j < 16; j++) {
            float m = s_mb[j];
            z0[j] = make_float2(m, m); z1[j] = z0[j]; z2[j] = z0[j];
        }

#pragma unroll
        for (int s = 0; s < 3; s++) {
            const float* bp = (s == 0 ? g_H0 : (s == 1 ? g_H1 : g_H2)) + off;
#pragma unroll
            for (int c = 0; c < 16; c++) {
                const float* p = bp + (size_t)c * TLEN;
                float2 h0 = *reinterpret_cast<const float2*>(p);
                float2 h1 = *reinterpret_cast<const float2*>(p + 2);
                float2 h2 = *reinterpret_cast<const float2*>(p + 4);
#pragma unroll
                for (int j = 0; j < 16; j++) {
                    float2 w = sg[j * 48 + s * 16 + c];
                    z0[j] = ffma2(w, h0, z0[j]);
                    z1[j] = ffma2(w, h1, z1[j]);
                    z2[j] = ffma2(w, h2, z2[j]);
                }
            }
        }

#pragma unroll
        for (int j = 0; j < 16; j++) {
            z0[j].x = fmaxf(z0[j].x, 0.f); z0[j].y = fmaxf(z0[j].y, 0.f);
            z1[j].x = fmaxf(z1[j].x, 0.f); z1[j].y = fmaxf(z1[j].y, 0.f);
            z2[j].x = fmaxf(z2[j].x, 0.f); z2[j].y = fmaxf(z2[j].y, 0.f);
        }

#pragma unroll
        for (int i2 = 0; i2 < 16; i2++) {
            float rb = s_rb1[i2];
            float2 a0 = make_float2(rb, rb), a1 = a0, a2 = a0;
#pragma unroll
            for (int j = 0; j < 16; j++) {
                float2 w = sr1[i2 * 16 + j];
                a0 = ffma2(w, z0[j], a0);
                a1 = ffma2(w, z1[j], a1);
                a2 = ffma2(w, z2[j], a2);
            }
            part[tid][i2] = fmaxf(a0.x, 0.f) + fmaxf(a0.y, 0.f)
                          + fmaxf(a1.x, 0.f) + fmaxf(a1.y, 0.f)
                          + fmaxf(a2.x, 0.f) + fmaxf(a2.y, 0.f);
        }
    }
    __syncthreads();

    if (tid < 128) {
        int b = tid >> 4, i = tid & 15;
        float s = 0.f;
#pragma unroll
        for (int k = 0; k < 27; k++) s += part[b * 27 + k][i];
        rm[b][i] = s * (1.f / (float)TLEN);
    }
    __syncthreads();

    if (tid < 192) {
        int b = tid / 24, o = tid - b * 24;
        float a = s_rb2[o];
#pragma unroll
        for (int c = 0; c < 16; c++) a += s_rw2[o * 16 + c] * rm[b][c];
        out[((size_t)b * 24 + o) * NNODE + v] = a;
    }
}

// ======================= launcher =======================
extern "C" void kernel_launch(void* const* d_in, const int* in_sizes, int n_in,
                              void* d_out, int out_size) {
    const float* x   = (const float*)d_in[0];
    const float* pw  = (const float*)d_in[1];
    const float* pb  = (const float*)d_in[2];
    const float* tw2 = (const float*)d_in[3];
    const float* tb2 = (const float*)d_in[4];
    const float* tw3 = (const float*)d_in[5];
    const float* tb3 = (const float*)d_in[6];
    const float* tw6 = (const float*)d_in[7];
    const float* tb6 = (const float*)d_in[8];
    const float* tw7 = (const float*)d_in[9];
    const float* tb7 = (const float*)d_in[10];
    const float* e1  = (const float*)d_in[11];
    const float* e2  = (const float*)d_in[12];
    const float* gw1 = (const float*)d_in[13];
    const float* gb1 = (const float*)d_in[14];
    const float* gw2 = (const float*)d_in[15];
    const float* gb2 = (const float*)d_in[16];
    const float* mw  = (const float*)d_in[17];
    const float* mb  = (const float*)d_in[18];
    const float* rw1 = (const float*)d_in[19];
    const float* rb1 = (const float*)d_in[20];
    const float* rw2 = (const float*)d_in[21];
    const float* rb2 = (const float*)d_in[22];

    k_prep_weff<<<1, 32>>>(pw, pb, tw2, tb2, tw3, tb3, tw6, tb6, tw7, tb7);
    k_prep_m<<<(NNODE + 127) / 128, 128>>>(e1, gw1, gb1, e2, gw2, gb2);
    k_topk<<<NNODE, 256>>>();
    k_tconv<<<NNODE, 192>>>(x);

    dim3 gs(NNODE, FDIM / 256);   // 1500 x 81
    k_spmm<<<gs, 256>>>(0);
    k_spmm<<<gs, 256>>>(1);

    k_final<<<NNODE, 224>>>(mw, mb, rw1, rb1, rw2, rb2, (float*)d_out);
}